// round 1
// baseline (speedup 1.0000x reference)
#include <cuda_runtime.h>
#include <cstdint>

#define N_NODES 4096
#define NNZV    110592
#define BATCH   128
#define RTOT    12288   // 3 * 4096 flattened (k*4096 + n)

// ---------------- static device scratch (no runtime allocation) ----------------
__device__ int   g_counts[N_NODES];
__device__ int   g_offsets[N_NODES + 1];
__device__ int   g_cursor[N_NODES];
__device__ int   g_ccol[NNZV];
__device__ float g_cval[NNZV];
__device__ float g_xT[N_NODES * BATCH];     // xT[m][b]
__device__ float g_x1[BATCH * N_NODES];     // x1[b][m]  (tf32-prerounded)
__device__ float g_P[2 * BATCH * RTOT];     // split-K partials of t

// ---------------- helpers ----------------
__device__ __forceinline__ uint32_t f2tf32(float x) {
    uint32_t r;
    asm("cvt.rna.tf32.f32 %0, %1;" : "=r"(r) : "f"(x));
    return r;
}

__device__ __forceinline__ void cp16(void* smem, const void* gmem) {
    uint32_t s = (uint32_t)__cvta_generic_to_shared(smem);
    asm volatile("cp.async.cg.shared.global [%0], [%1], 16;\n" :: "r"(s), "l"(gmem));
}

__device__ __forceinline__ void ldsm4(uint32_t* r, uint32_t addr) {
    asm volatile("ldmatrix.sync.aligned.m8n8.x4.shared.b16 {%0,%1,%2,%3}, [%4];"
                 : "=r"(r[0]), "=r"(r[1]), "=r"(r[2]), "=r"(r[3]) : "r"(addr));
}

__device__ __forceinline__ void mma_tf32(float* c, const uint32_t* a, const uint32_t* b) {
    asm volatile("mma.sync.aligned.m16n8k8.row.col.f32.tf32.tf32.f32 "
                 "{%0,%1,%2,%3}, {%4,%5,%6,%7}, {%8,%9}, {%0,%1,%2,%3};"
                 : "+f"(c[0]), "+f"(c[1]), "+f"(c[2]), "+f"(c[3])
                 : "r"(a[0]), "r"(a[1]), "r"(a[2]), "r"(a[3]), "r"(b[0]), "r"(b[1]));
}

__device__ __forceinline__ float selu_f(float v) {
    const float scale = 1.0507009873554805f;
    const float alpha = 1.6732632423543772f;
    return v > 0.f ? scale * v : scale * alpha * expm1f(v);
}

// ---------------- CSR build ----------------
__global__ void zero_counts_kernel() {
    int i = blockIdx.x * blockDim.x + threadIdx.x;
    if (i < N_NODES) g_counts[i] = 0;
}

__global__ void count_kernel(const int* __restrict__ rows) {
    int i = blockIdx.x * blockDim.x + threadIdx.x;
    if (i < NNZV) atomicAdd(&g_counts[rows[i]], 1);
}

__global__ void scan_kernel() {
    __shared__ int sm[1024];
    int t = threadIdx.x;
    int c0 = g_counts[4 * t + 0];
    int c1 = g_counts[4 * t + 1];
    int c2 = g_counts[4 * t + 2];
    int c3 = g_counts[4 * t + 3];
    int local = c0 + c1 + c2 + c3;
    sm[t] = local;
    __syncthreads();
    for (int off = 1; off < 1024; off <<= 1) {
        int v = (t >= off) ? sm[t - off] : 0;
        __syncthreads();
        sm[t] += v;
        __syncthreads();
    }
    int excl = sm[t] - local;
    int o0 = excl, o1 = o0 + c0, o2 = o1 + c1, o3 = o2 + c2;
    g_offsets[4 * t + 0] = o0; g_cursor[4 * t + 0] = o0;
    g_offsets[4 * t + 1] = o1; g_cursor[4 * t + 1] = o1;
    g_offsets[4 * t + 2] = o2; g_cursor[4 * t + 2] = o2;
    g_offsets[4 * t + 3] = o3; g_cursor[4 * t + 3] = o3;
    if (t == 1023) g_offsets[N_NODES] = sm[1023];
}

__global__ void scatter_kernel(const int* __restrict__ rows,
                               const int* __restrict__ cols,
                               const float* __restrict__ vals) {
    int i = blockIdx.x * blockDim.x + threadIdx.x;
    if (i < NNZV) {
        int r = rows[i];
        int p = atomicAdd(&g_cursor[r], 1);
        g_ccol[p] = cols[i];
        g_cval[p] = vals[i];
    }
}

// ---------------- transpose x [128,4096] -> xT [4096,128] ----------------
__global__ void transpose_kernel(const float* __restrict__ x) {
    __shared__ float tile[32][33];
    int bm = blockIdx.x * 32;   // node dim
    int bb = blockIdx.y * 32;   // batch dim
    int tx = threadIdx.x, ty = threadIdx.y;
    #pragma unroll
    for (int i = 0; i < 32; i += 8)
        tile[ty + i][tx] = x[(size_t)(bb + ty + i) * N_NODES + bm + tx];
    __syncthreads();
    #pragma unroll
    for (int i = 0; i < 32; i += 8)
        g_xT[(size_t)(bm + ty + i) * BATCH + bb + tx] = tile[tx][ty + i];
}

// ---------------- SpMV + bc/flag, tf32 preround ----------------
__global__ void spmv_kernel(const float* __restrict__ bc, const float* __restrict__ flag) {
    int m = blockIdx.x;       // node / row
    int b = threadIdx.x;      // batch
    int s = g_offsets[m];
    int e = g_offsets[m + 1];
    float acc = 0.f;
    for (int j = s; j < e; j++) {
        int   c = __ldg(&g_ccol[j]);
        float v = __ldg(&g_cval[j]);
        acc += v * g_xT[(size_t)c * BATCH + b];
    }
    float r = bc[m] + acc * flag[m];
    g_x1[(size_t)b * N_NODES + m] = __uint_as_float(f2tf32(r));
}

// ---------------- tf32 GEMM: P[ks][b][r] = sum_{m in kslice} x1[b][m] * W[r][m] --------
// W = weight1 flat [12288][4096]; BM=128, BN=128, BK=16, split-K = 2, grid = 96*2
#define GBM 128
#define GBN 128
#define GBK 16
#define LDSH 20            // GBK + 4 pad
#define KSPLIT 2
#define KPER (N_NODES / KSPLIT)   // 2048
#define KT  (KPER / GBK)          // 128
#define NRT (RTOT / GBN)          // 96

__global__ void __launch_bounds__(256) gemm_tf32_kernel(const float* __restrict__ W) {
    __shared__ __align__(16) float As[2][GBM * LDSH];
    __shared__ __align__(16) float Bs[2][GBN * LDSH];

    int tid = threadIdx.x;
    int bx  = blockIdx.x;
    int rt  = bx % NRT;
    int ks  = bx / NRT;
    int r0  = rt * GBN;
    int k0  = ks * KPER;

    int warp = tid >> 5;
    int lane = tid & 31;
    int wm = warp >> 2;   // 0..1 -> 64 rows each
    int wn = warp & 3;    // 0..3 -> 32 cols each

    int row_sel = (lane & 7) + ((lane >> 3) & 1) * 8;
    int kofs    = (lane >> 4) * 4;

    float acc[4][4][4];
    #pragma unroll
    for (int i = 0; i < 4; i++)
        #pragma unroll
        for (int j = 0; j < 4; j++)
            #pragma unroll
            for (int q = 0; q < 4; q++) acc[i][j][q] = 0.f;

    uint32_t as_base = (uint32_t)__cvta_generic_to_shared(&As[0][0]);

#define STAGE(bufi, kti) do {                                                     \
        int kk = k0 + (kti) * GBK;                                                \
        _Pragma("unroll")                                                         \
        for (int j = 0; j < 2; j++) {                                             \
            int c = tid + j * 256; int row = c >> 2, kq = c & 3;                  \
            cp16(&As[bufi][row * LDSH + kq * 4],                                  \
                 &g_x1[(size_t)row * N_NODES + kk + kq * 4]);                     \
        }                                                                         \
        _Pragma("unroll")                                                         \
        for (int j = 0; j < 2; j++) {                                             \
            int c = tid + j * 256; int row = c >> 2, kq = c & 3;                  \
            cp16(&Bs[bufi][row * LDSH + kq * 4],                                  \
                 &W[(size_t)(r0 + row) * N_NODES + kk + kq * 4]);                 \
        }                                                                         \
    } while (0)

    STAGE(0, 0);
    asm volatile("cp.async.commit_group;\n");

    for (int kt = 0; kt < KT; kt++) {
        int buf = kt & 1;
        if (kt + 1 < KT) {
            STAGE(buf ^ 1, kt + 1);
            asm volatile("cp.async.commit_group;\n");
            asm volatile("cp.async.wait_group 1;\n");
        } else {
            asm volatile("cp.async.wait_group 0;\n");
        }
        __syncthreads();

        #pragma unroll
        for (int ksx = 0; ksx < 2; ksx++) {
            uint32_t a[4][4];
            #pragma unroll
            for (int mt = 0; mt < 4; mt++) {
                uint32_t ad = as_base +
                    (uint32_t)((buf * GBM * LDSH +
                                (wm * 64 + mt * 16 + row_sel) * LDSH +
                                ksx * 8 + kofs) * 4);
                ldsm4(a[mt], ad);
            }
            uint32_t bfr[4][2];
            #pragma unroll
            for (int nt = 0; nt < 4; nt++) {
                int rrow = wn * 32 + nt * 8 + (lane >> 2);
                float b0 = Bs[buf][rrow * LDSH + ksx * 8 + (lane & 3)];
                float b1 = Bs[buf][rrow * LDSH + ksx * 8 + (lane & 3) + 4];
                bfr[nt][0] = f2tf32(b0);
                bfr[nt][1] = f2tf32(b1);
            }
            #pragma unroll
            for (int mt = 0; mt < 4; mt++)
                #pragma unroll
                for (int nt = 0; nt < 4; nt++)
                    mma_tf32(acc[mt][nt], a[mt], bfr[nt]);
        }
        __syncthreads();
    }

    // epilogue: write raw partials to g_P[ks]
    float* Pp = g_P + (size_t)ks * BATCH * RTOT;
    #pragma unroll
    for (int mt = 0; mt < 4; mt++) {
        int row = wm * 64 + mt * 16 + (lane >> 2);
        #pragma unroll
        for (int nt = 0; nt < 4; nt++) {
            int col = r0 + wn * 32 + nt * 8 + (lane & 3) * 2;
            float2 v0 = make_float2(acc[mt][nt][0], acc[mt][nt][1]);
            float2 v1 = make_float2(acc[mt][nt][2], acc[mt][nt][3]);
            *(float2*)&Pp[(size_t)row * RTOT + col]       = v0;
            *(float2*)&Pp[(size_t)(row + 8) * RTOT + col] = v1;
        }
    }
#undef STAGE
}

// ---------------- finalize: sum splits, selu*w2, sum over k, bc + flag -------
__global__ void finalize_kernel(const float* __restrict__ bc,
                                const float* __restrict__ flag,
                                const float* __restrict__ w2,
                                float* __restrict__ out) {
    int idx = blockIdx.x * blockDim.x + threadIdx.x;   // < 128*4096
    int b = idx >> 12;
    int n = idx & 4095;
    const float* P0 = g_P;
    const float* P1 = g_P + (size_t)BATCH * RTOT;
    size_t base = (size_t)b * RTOT + n;
    float t0 = P0[base]        + P1[base];
    float t1 = P0[base + 4096] + P1[base + 4096];
    float t2 = P0[base + 8192] + P1[base + 8192];
    float s = selu_f(t0) * w2[n * 3 + 0]
            + selu_f(t1) * w2[n * 3 + 1]
            + selu_f(t2) * w2[n * 3 + 2];
    out[idx] = bc[n] + s * flag[n];
}

// ---------------- launch ----------------
extern "C" void kernel_launch(void* const* d_in, const int* in_sizes, int n_in,
                              void* d_out, int out_size) {
    const float* x     = (const float*)d_in[0];
    const float* bc    = (const float*)d_in[1];
    const float* flag  = (const float*)d_in[2];
    const int*   Brows = (const int*)d_in[3];
    const int*   Bcols = (const int*)d_in[4];
    const float* Bvals = (const float*)d_in[5];
    const float* w1    = (const float*)d_in[6];
    const float* w2    = (const float*)d_in[7];
    float* out = (float*)d_out;

    zero_counts_kernel<<<N_NODES / 256, 256>>>();
    count_kernel<<<NNZV / 256, 256>>>(Brows);
    scan_kernel<<<1, 1024>>>();
    scatter_kernel<<<NNZV / 256, 256>>>(Brows, Bcols, Bvals);
    transpose_kernel<<<dim3(N_NODES / 32, BATCH / 32), dim3(32, 8)>>>(x);
    spmv_kernel<<<N_NODES, BATCH>>>(bc, flag);
    gemm_tf32_kernel<<<NRT * KSPLIT, 256>>>(w1);
    finalize_kernel<<<(BATCH * N_NODES) / 256, 256>>>(bc, flag, w2, out);
}

// round 3
// speedup vs baseline: 1.6020x; 1.6020x over previous
#include <cuda_runtime.h>
#include <cstdint>

#define N_NODES 4096
#define NNZV    110592
#define BATCH   128
#define RTOT    12288   // 3 * 4096 flattened (k*4096 + n)

// ---------------- static device scratch ----------------
__device__ int   g_counts[N_NODES];
__device__ int   g_offsets[N_NODES + 1];
__device__ int   g_cursor[N_NODES];
__device__ int   g_ccol[NNZV];
__device__ float g_cval[NNZV];
__device__ float g_xT[N_NODES * BATCH];     // xT[m][b]
__device__ float g_x1[BATCH * N_NODES];     // x1[b][m]  (tf32-rna-prerounded)
__device__ float g_P[BATCH * RTOT];         // t accumulators: P[b][r]

// ---------------- helpers ----------------
__device__ __forceinline__ uint32_t smem_u32(const void* p) {
    return (uint32_t)__cvta_generic_to_shared(p);
}

__device__ __forceinline__ uint32_t f2tf32(float x) {
    uint32_t r;
    asm("cvt.rna.tf32.f32 %0, %1;" : "=r"(r) : "f"(x));
    return r;
}

__device__ __forceinline__ void cp16s(uint32_t saddr, const void* g) {
    asm volatile("cp.async.cg.shared.global [%0], [%1], 16;" :: "r"(saddr), "l"(g));
}
#define CP_COMMIT() asm volatile("cp.async.commit_group;" ::: "memory")

__device__ __forceinline__ void ldsm4(uint32_t* r, uint32_t addr) {
    asm volatile("ldmatrix.sync.aligned.m8n8.x4.shared.b16 {%0,%1,%2,%3}, [%4];"
                 : "=r"(r[0]), "=r"(r[1]), "=r"(r[2]), "=r"(r[3]) : "r"(addr));
}

__device__ __forceinline__ void mma_tf32(float* c, const uint32_t* a, const uint32_t* b) {
    asm volatile("mma.sync.aligned.m16n8k8.row.col.f32.tf32.tf32.f32 "
                 "{%0,%1,%2,%3}, {%4,%5,%6,%7}, {%8,%9}, {%0,%1,%2,%3};"
                 : "+f"(c[0]), "+f"(c[1]), "+f"(c[2]), "+f"(c[3])
                 : "r"(a[0]), "r"(a[1]), "r"(a[2]), "r"(a[3]), "r"(b[0]), "r"(b[1]));
}

__device__ __forceinline__ void redadd(float* p, float v) {
    asm volatile("red.global.add.f32 [%0], %1;" :: "l"(p), "f"(v) : "memory");
}

__device__ __forceinline__ float selu_f(float v) {
    const float scale = 1.0507009873554805f;
    const float alpha = 1.6732632423543772f;
    return v > 0.f ? scale * v : scale * alpha * expm1f(v);
}

// ---------------- preprocessing ----------------
// transpose x [128,4096] -> xT [4096,128]; also zero g_counts
__global__ void transpose_kernel(const float* __restrict__ x) {
    __shared__ float tile[32][33];
    int bid = blockIdx.y * gridDim.x + blockIdx.x;
    int t = threadIdx.y * 32 + threadIdx.x;
    int gidx = bid * 256 + t;
    if (gidx < N_NODES) g_counts[gidx] = 0;

    int bm = blockIdx.x * 32;
    int bb = blockIdx.y * 32;
    int tx = threadIdx.x, ty = threadIdx.y;
    #pragma unroll
    for (int i = 0; i < 32; i += 8)
        tile[ty + i][tx] = x[(size_t)(bb + ty + i) * N_NODES + bm + tx];
    __syncthreads();
    #pragma unroll
    for (int i = 0; i < 32; i += 8)
        g_xT[(size_t)(bm + ty + i) * BATCH + bb + tx] = tile[tx][ty + i];
}

// count rows; also zero g_P (must finish before gemm, same stream)
__global__ void count_kernel(const int* __restrict__ rows) {
    int i = blockIdx.x * blockDim.x + threadIdx.x;
    if (i < NNZV) atomicAdd(&g_counts[rows[i]], 1);
    float4* P4 = (float4*)g_P;
    const int total4 = BATCH * RTOT / 4;                 // 393216
    const int nthreads = (NNZV / 256) * 256;             // 110592
    for (int j = i; j < total4; j += nthreads)
        P4[j] = make_float4(0.f, 0.f, 0.f, 0.f);
}

__global__ void scan_kernel() {
    __shared__ int sm[1024];
    int t = threadIdx.x;
    int c0 = g_counts[4 * t + 0];
    int c1 = g_counts[4 * t + 1];
    int c2 = g_counts[4 * t + 2];
    int c3 = g_counts[4 * t + 3];
    int local = c0 + c1 + c2 + c3;
    sm[t] = local;
    __syncthreads();
    for (int off = 1; off < 1024; off <<= 1) {
        int v = (t >= off) ? sm[t - off] : 0;
        __syncthreads();
        sm[t] += v;
        __syncthreads();
    }
    int excl = sm[t] - local;
    int o0 = excl, o1 = o0 + c0, o2 = o1 + c1, o3 = o2 + c2;
    g_offsets[4 * t + 0] = o0; g_cursor[4 * t + 0] = o0;
    g_offsets[4 * t + 1] = o1; g_cursor[4 * t + 1] = o1;
    g_offsets[4 * t + 2] = o2; g_cursor[4 * t + 2] = o2;
    g_offsets[4 * t + 3] = o3; g_cursor[4 * t + 3] = o3;
    if (t == 1023) g_offsets[N_NODES] = sm[1023];
}

__global__ void scatter_kernel(const int* __restrict__ rows,
                               const int* __restrict__ cols,
                               const float* __restrict__ vals) {
    int i = blockIdx.x * blockDim.x + threadIdx.x;
    if (i < NNZV) {
        int r = rows[i];
        int p = atomicAdd(&g_cursor[r], 1);
        g_ccol[p] = cols[i];
        g_cval[p] = vals[i];
    }
}

// SpMV + bc/flag, rna-preround to tf32 grid
__global__ void spmv_kernel(const float* __restrict__ bc, const float* __restrict__ flag) {
    int m = blockIdx.x;
    int b = threadIdx.x;
    int s = g_offsets[m];
    int e = g_offsets[m + 1];
    float acc = 0.f;
    for (int j = s; j < e; j++) {
        int   c = __ldg(&g_ccol[j]);
        float v = __ldg(&g_cval[j]);
        acc += v * g_xT[(size_t)c * BATCH + b];
    }
    float r = bc[m] + acc * flag[m];
    g_x1[(size_t)b * N_NODES + m] = __uint_as_float(f2tf32(r));
}

// ---------------- stream-K tf32 mma.sync GEMM ----------------
// D[m=batch][n=W-row] = sum_k x1[m][k] * W[n][k]
// Tiles: 96 N-tiles of 128 W-rows, M=128 (full batch), K chunks of 32.
// 12288 (tile,chunk) units distributed evenly over 148 CTAs; partials
// accumulated into pre-zeroed g_P via red.global.
#define BK2   32
#define LDS2  36                      // floats per smem row (32 + 4 pad)
#define ROWB  (LDS2 * 4)              // 144 bytes
#define STG_BYTES (128 * ROWB)        // 18432
#define NST   3
#define B_OFF (NST * STG_BYTES)
#define GSM_TOTAL (2 * NST * STG_BYTES)   // 110592
#define CHT   (N_NODES / BK2)         // 128 chunks per tile
#define NTILE (RTOT / 128)            // 96
#define UNITS (NTILE * CHT)           // 12288
#define GRID_SK 148

__device__ __forceinline__ void fill_stage2(uint32_t sb, int tid,
                                            const float* __restrict__ Wt,
                                            int s, int kk) {
    uint32_t ab = sb + s * STG_BYTES;
    uint32_t bb = sb + B_OFF + s * STG_BYTES;
    #pragma unroll
    for (int j = 0; j < 4; j++) {
        int id  = tid + j * 256;        // 0..1023
        int row = id >> 3;
        int sg  = id & 7;
        uint32_t off = (uint32_t)(row * ROWB + sg * 16);
        cp16s(ab + off, g_x1 + (size_t)row * N_NODES + kk + sg * 4);
        cp16s(bb + off, Wt   + (size_t)row * N_NODES + kk + sg * 4);
    }
}

__global__ void __launch_bounds__(256) gemm_sk_kernel(const float* __restrict__ W) {
    extern __shared__ char sm2[];
    uint32_t sb = smem_u32(sm2);
    float* smB = (float*)(sm2 + B_OFF);

    int tid  = threadIdx.x;
    int lane = tid & 31;
    int warp = tid >> 5;
    int wm = warp >> 2;                 // 0..1  (64 batch-rows each)
    int wn = warp & 3;                  // 0..3  (32 W-rows each)
    int row_sel = (lane & 7) + ((lane >> 3) & 1) * 8;
    int kofs    = (lane >> 4) * 4;

    const int base = UNITS / GRID_SK;   // 83
    const int rem  = UNITS - base * GRID_SK;  // 4
    int c = blockIdx.x;
    int u   = c * base + (c < rem ? c : rem);
    int end = u + base + (c < rem ? 1 : 0);

    while (u < end) {
        int tile = u >> 7;              // /CHT
        int kc0  = u & (CHT - 1);
        int seg  = CHT - kc0;
        if (seg > end - u) seg = end - u;
        const float* Wt = W + (size_t)tile * 128 * N_NODES;

        float acc[4][4][4];
        #pragma unroll
        for (int i = 0; i < 4; i++)
            #pragma unroll
            for (int j = 0; j < 4; j++)
                #pragma unroll
                for (int q = 0; q < 4; q++) acc[i][j][q] = 0.f;

        // prologue
        int pro = (seg < NST - 1) ? seg : (NST - 1);
        #pragma unroll
        for (int s = 0; s < NST - 1; s++) {
            if (s < pro) {
                fill_stage2(sb, tid, Wt, s, (kc0 + s) * BK2);
                CP_COMMIT();
            }
        }

        int s  = 0;                     // stage of chunk kt
        int sf = 2;                     // stage of chunk kt+2
        for (int kt = 0; kt < seg; kt++) {
            if (kt + 1 < seg) asm volatile("cp.async.wait_group 1;" ::: "memory");
            else              asm volatile("cp.async.wait_group 0;" ::: "memory");
            __syncthreads();

            uint32_t ab = sb + s * STG_BYTES;
            const float* Bst = smB + (size_t)s * (STG_BYTES / 4);

            #pragma unroll
            for (int ksx = 0; ksx < 4; ksx++) {
                uint32_t a[4][4];
                #pragma unroll
                for (int mt = 0; mt < 4; mt++) {
                    uint32_t ad = ab + (uint32_t)(((wm * 64 + mt * 16 + row_sel) * LDS2
                                                   + ksx * 8 + kofs) * 4);
                    ldsm4(a[mt], ad);
                }
                uint32_t bf[4][2];
                #pragma unroll
                for (int nt = 0; nt < 4; nt++) {
                    int rrw = wn * 32 + nt * 8 + (lane >> 2);
                    bf[nt][0] = __float_as_uint(Bst[rrw * LDS2 + ksx * 8 + (lane & 3)]);
                    bf[nt][1] = __float_as_uint(Bst[rrw * LDS2 + ksx * 8 + (lane & 3) + 4]);
                }
                #pragma unroll
                for (int mt = 0; mt < 4; mt++)
                    #pragma unroll
                    for (int nt = 0; nt < 4; nt++)
                        mma_tf32(acc[mt][nt], a[mt], bf[nt]);
            }

            if (kt + 2 < seg) {
                fill_stage2(sb, tid, Wt, sf, (kc0 + kt + 2) * BK2);
                CP_COMMIT();
            }
            s  = (s  == 2) ? 0 : s + 1;
            sf = (sf == 2) ? 0 : sf + 1;
        }

        __syncthreads();   // all MMAs done before next segment's fills / epilogue overlap

        // epilogue: accumulate partials
        float* Pb = g_P + (size_t)tile * 128;
        #pragma unroll
        for (int mt = 0; mt < 4; mt++) {
            int m0 = wm * 64 + mt * 16 + (lane >> 2);
            #pragma unroll
            for (int nt = 0; nt < 4; nt++) {
                int n0 = wn * 32 + nt * 8 + ((lane & 3) << 1);
                redadd(&Pb[(size_t)m0 * RTOT + n0],           acc[mt][nt][0]);
                redadd(&Pb[(size_t)m0 * RTOT + n0 + 1],       acc[mt][nt][1]);
                redadd(&Pb[(size_t)(m0 + 8) * RTOT + n0],     acc[mt][nt][2]);
                redadd(&Pb[(size_t)(m0 + 8) * RTOT + n0 + 1], acc[mt][nt][3]);
            }
        }
        u += seg;
    }
}

// ---------------- finalize: bias-corrected selu*w2, bc + flag -------
// W fed to MMA as raw f32 bits -> hardware RZ-truncates to tf32: deterministic
// low bias E[rel] = 2^-11 * E[1/m] = 3.52e-4. Undo on t before selu.
#define TF32_RZ_CORR 1.0003522f

__global__ void finalize_kernel(const float* __restrict__ bc,
                                const float* __restrict__ flag,
                                const float* __restrict__ w2,
                                float* __restrict__ out) {
    int idx = blockIdx.x * blockDim.x + threadIdx.x;   // < 128*4096
    int b = idx >> 12;
    int n = idx & 4095;
    size_t base = (size_t)b * RTOT + n;
    float t0 = g_P[base]        * TF32_RZ_CORR;
    float t1 = g_P[base + 4096] * TF32_RZ_CORR;
    float t2 = g_P[base + 8192] * TF32_RZ_CORR;
    float s = selu_f(t0) * __ldg(&w2[n * 3 + 0])
            + selu_f(t1) * __ldg(&w2[n * 3 + 1])
            + selu_f(t2) * __ldg(&w2[n * 3 + 2]);
    out[idx] = bc[n] + s * flag[n];
}

// ---------------- launch ----------------
extern "C" void kernel_launch(void* const* d_in, const int* in_sizes, int n_in,
                              void* d_out, int out_size) {
    const float* x     = (const float*)d_in[0];
    const float* bc    = (const float*)d_in[1];
    const float* flag  = (const float*)d_in[2];
    const int*   Brows = (const int*)d_in[3];
    const int*   Bcols = (const int*)d_in[4];
    const float* Bvals = (const float*)d_in[5];
    const float* w1    = (const float*)d_in[6];
    const float* w2    = (const float*)d_in[7];
    float* out = (float*)d_out;

    cudaFuncSetAttribute(gemm_sk_kernel,
                         cudaFuncAttributeMaxDynamicSharedMemorySize, GSM_TOTAL);

    transpose_kernel<<<dim3(N_NODES / 32, BATCH / 32), dim3(32, 8)>>>(x);   // 1
    count_kernel<<<NNZV / 256, 256>>>(Brows);                               // 2 (+zero g_P)
    scan_kernel<<<1, 1024>>>();                                             // 3
    scatter_kernel<<<NNZV / 256, 256>>>(Brows, Bcols, Bvals);               // 4
    spmv_kernel<<<N_NODES, BATCH>>>(bc, flag);                              // 5
    gemm_sk_kernel<<<GRID_SK, 256, GSM_TOTAL>>>(w1);                        // 6 (ncu -s 5)
    finalize_kernel<<<(BATCH * N_NODES) / 256, 256>>>(bc, flag, w2, out);   // 7
}

// round 4
// speedup vs baseline: 1.6902x; 1.0551x over previous
#include <cuda_runtime.h>
#include <cstdint>

#define N_NODES 4096
#define NNZV    110592
#define BATCH   128
#define RTOT    12288   // 3 * 4096 flattened (k*4096 + n)
#define NCTA_PREP 148

// ---------------- static device scratch ----------------
__device__ int   g_counts[N_NODES];
__device__ int   g_offsets[N_NODES + 1];
__device__ int   g_cursor[N_NODES];
__device__ int   g_ccol[NNZV];
__device__ float g_cval[NNZV];
__device__ float g_xT[N_NODES * BATCH];       // xT[m][b]
__device__ float g_x1[BATCH * N_NODES];       // x1[b][m]  (tf32-rna-prerounded)
__device__ float g_P3[3 * BATCH * RTOT];      // 3 partial slots
__device__ int   g_bars[4];                   // grid barrier counters (zeroed by finalize)

// ---------------- helpers ----------------
__device__ __forceinline__ uint32_t smem_u32(const void* p) {
    return (uint32_t)__cvta_generic_to_shared(p);
}

__device__ __forceinline__ uint32_t f2tf32(float x) {
    uint32_t r;
    asm("cvt.rna.tf32.f32 %0, %1;" : "=r"(r) : "f"(x));
    return r;
}

__device__ __forceinline__ void cp16s(uint32_t saddr, const void* g) {
    asm volatile("cp.async.cg.shared.global [%0], [%1], 16;" :: "r"(saddr), "l"(g));
}
#define CP_COMMIT() asm volatile("cp.async.commit_group;" ::: "memory")

__device__ __forceinline__ void ldsm4(uint32_t* r, uint32_t addr) {
    asm volatile("ldmatrix.sync.aligned.m8n8.x4.shared.b16 {%0,%1,%2,%3}, [%4];"
                 : "=r"(r[0]), "=r"(r[1]), "=r"(r[2]), "=r"(r[3]) : "r"(addr));
}

__device__ __forceinline__ void mma_tf32(float* c, const uint32_t* a, const uint32_t* b) {
    asm volatile("mma.sync.aligned.m16n8k8.row.col.f32.tf32.tf32.f32 "
                 "{%0,%1,%2,%3}, {%4,%5,%6,%7}, {%8,%9}, {%0,%1,%2,%3};"
                 : "+f"(c[0]), "+f"(c[1]), "+f"(c[2]), "+f"(c[3])
                 : "r"(a[0]), "r"(a[1]), "r"(a[2]), "r"(a[3]), "r"(b[0]), "r"(b[1]));
}

__device__ __forceinline__ float selu_f(float v) {
    const float scale = 1.0507009873554805f;
    const float alpha = 1.6732632423543772f;
    return v > 0.f ? scale * v : scale * alpha * expm1f(v);
}

// grid-wide barrier; k-th epoch. g_bars zeroed by finalize each run.
__device__ __forceinline__ void gbar(int k) {
    __syncthreads();
    if (threadIdx.x == 0) {
        __threadfence();
        atomicAdd(&g_bars[k], 1);
        for (;;) {
            int v;
            asm volatile("ld.acquire.gpu.global.s32 %0, [%1];"
                         : "=r"(v) : "l"(&g_bars[k]) : "memory");
            if (v >= NCTA_PREP) break;
            __nanosleep(64);
        }
    }
    __syncthreads();
}

// ---------------- fused preprocessing kernel ----------------
// phases: p0 zero(counts, P3 slots 1&2) + transpose | p1 count | p2 scan(CTA0)
//         | p3 scatter | p4 spmv + x1 store (smem-transposed)
__global__ void __launch_bounds__(1024, 1) prep_kernel(
    const float* __restrict__ x,
    const float* __restrict__ bc,
    const float* __restrict__ flag,
    const int*   __restrict__ rows,
    const int*   __restrict__ cols,
    const float* __restrict__ vals)
{
    __shared__ union {
        float t4[4][32][33];    // transpose tiles
        int   sc[1024];         // scan
        float xr[32][129];      // spmv staging (padded: conflict-free)
    } sh;

    const int tid = threadIdx.x;
    const int cta = blockIdx.x;
    const int gth = NCTA_PREP * 1024;
    const int gid = cta * 1024 + tid;

    // ---- p0 ----
    for (int i = gid; i < N_NODES; i += gth) g_counts[i] = 0;
    {
        float4* p4 = (float4*)(g_P3 + (size_t)BATCH * RTOT);   // slots 1,2
        const int tot = 2 * BATCH * RTOT / 4;
        for (int i = gid; i < tot; i += gth) p4[i] = make_float4(0.f, 0.f, 0.f, 0.f);
    }
    {   // transpose x[128,4096] -> xT[4096,128]: 512 tiles of 32x32
        int sub = tid >> 8;             // 0..3
        int t2  = tid & 255;
        int tx  = t2 & 31;
        int ty  = t2 >> 5;              // 0..7
        int tix = sub * NCTA_PREP + cta;
        bool act = tix < 512;
        int bm = (tix & 127) * 32;
        int bb = (tix >> 7) * 32;
        if (act) {
            #pragma unroll
            for (int i = 0; i < 32; i += 8)
                sh.t4[sub][ty + i][tx] = x[(size_t)(bb + ty + i) * N_NODES + bm + tx];
        }
        __syncthreads();
        if (act) {
            #pragma unroll
            for (int i = 0; i < 32; i += 8)
                g_xT[(size_t)(bm + ty + i) * BATCH + bb + tx] = sh.t4[sub][tx][ty + i];
        }
    }
    gbar(0);

    // ---- p1: count ----
    for (int i = gid; i < NNZV; i += gth) atomicAdd(&g_counts[rows[i]], 1);
    gbar(1);

    // ---- p2: scan (CTA0 only) ----
    if (cta == 0) {
        int t = tid;
        int c0 = g_counts[4 * t + 0];
        int c1 = g_counts[4 * t + 1];
        int c2 = g_counts[4 * t + 2];
        int c3 = g_counts[4 * t + 3];
        int local = c0 + c1 + c2 + c3;
        sh.sc[t] = local;
        __syncthreads();
        for (int off = 1; off < 1024; off <<= 1) {
            int v = (t >= off) ? sh.sc[t - off] : 0;
            __syncthreads();
            sh.sc[t] += v;
            __syncthreads();
        }
        int excl = sh.sc[t] - local;
        int o0 = excl, o1 = o0 + c0, o2 = o1 + c1, o3 = o2 + c2;
        g_offsets[4 * t + 0] = o0; g_cursor[4 * t + 0] = o0;
        g_offsets[4 * t + 1] = o1; g_cursor[4 * t + 1] = o1;
        g_offsets[4 * t + 2] = o2; g_cursor[4 * t + 2] = o2;
        g_offsets[4 * t + 3] = o3; g_cursor[4 * t + 3] = o3;
        if (t == 1023) g_offsets[N_NODES] = sh.sc[1023];
    }
    gbar(2);

    // ---- p3: scatter ----
    for (int i = gid; i < NNZV; i += gth) {
        int r = rows[i];
        int p = atomicAdd(&g_cursor[r], 1);
        g_ccol[p] = cols[i];
        g_cval[p] = vals[i];
    }
    gbar(3);

    // ---- p4: spmv + x1 (warp = one node-row; smem-transposed store) ----
    const int w    = tid >> 5;
    const int lane = tid & 31;
    for (int rb = cta; rb < N_NODES / 32; rb += NCTA_PREP) {
        int m = rb * 32 + w;
        int s = g_offsets[m];
        int e = g_offsets[m + 1];
        float a0 = 0.f, a1 = 0.f, a2 = 0.f, a3 = 0.f;
        for (int j = s; j < e; j++) {
            int   c = __ldg(&g_ccol[j]);
            float v = __ldg(&g_cval[j]);
            const float* xr = g_xT + (size_t)c * BATCH;
            a0 += v * xr[lane];
            a1 += v * xr[lane + 32];
            a2 += v * xr[lane + 64];
            a3 += v * xr[lane + 96];
        }
        float f = flag[m], bv = bc[m];
        sh.xr[w][lane]      = __uint_as_float(f2tf32(bv + a0 * f));
        sh.xr[w][lane + 32] = __uint_as_float(f2tf32(bv + a1 * f));
        sh.xr[w][lane + 64] = __uint_as_float(f2tf32(bv + a2 * f));
        sh.xr[w][lane + 96] = __uint_as_float(f2tf32(bv + a3 * f));
        __syncthreads();
        {   // write x1[b][rb*32 .. +32): thread -> (b, 4 consecutive m)
            int b  = tid >> 3;
            int mq = (tid & 7) * 4;
            float4 v;
            v.x = sh.xr[mq + 0][b];
            v.y = sh.xr[mq + 1][b];
            v.z = sh.xr[mq + 2][b];
            v.w = sh.xr[mq + 3][b];
            *(float4*)&g_x1[(size_t)b * N_NODES + rb * 32 + mq] = v;
        }
        __syncthreads();
    }
}

// ---------------- stream-K tf32 mma.sync GEMM ----------------
// D[m=batch][n=W-row] = sum_k x1[m][k] * W[n][k]
// 96 N-tiles x 128 K-chunks = 12288 units over 148 CTAs.
// Each tile is cut into <=3 segments (83 < 128 < 166); partials go to
// deterministic slot: 0 if segment starts tile, else 1 + (cta & 1).
#define BK2   32
#define LDS2  36
#define ROWB  (LDS2 * 4)              // 144
#define STG_BYTES (128 * ROWB)        // 18432
#define NST   3
#define B_OFF (NST * STG_BYTES)
#define GSM_TOTAL (2 * NST * STG_BYTES)   // 110592
#define CHT   (N_NODES / BK2)         // 128
#define NTILE (RTOT / 128)            // 96
#define UNITS (NTILE * CHT)           // 12288
#define GRID_SK 148

__device__ __forceinline__ void fill_stage2(uint32_t sb, int tid,
                                            const float* __restrict__ Wt,
                                            int s, int kk) {
    uint32_t ab = sb + s * STG_BYTES;
    uint32_t bb = sb + B_OFF + s * STG_BYTES;
    #pragma unroll
    for (int j = 0; j < 4; j++) {
        int id  = tid + j * 256;
        int row = id >> 3;
        int sg  = id & 7;
        uint32_t off = (uint32_t)(row * ROWB + sg * 16);
        cp16s(ab + off, g_x1 + (size_t)row * N_NODES + kk + sg * 4);
        cp16s(bb + off, Wt   + (size_t)row * N_NODES + kk + sg * 4);
    }
}

__global__ void __launch_bounds__(256) gemm_sk_kernel(const float* __restrict__ W) {
    extern __shared__ char sm2[];
    uint32_t sb = smem_u32(sm2);
    float* smB = (float*)(sm2 + B_OFF);

    int tid  = threadIdx.x;
    int lane = tid & 31;
    int warp = tid >> 5;
    int wm = warp >> 2;
    int wn = warp & 3;
    int row_sel = (lane & 7) + ((lane >> 3) & 1) * 8;
    int kofs    = (lane >> 4) * 4;

    const int base = UNITS / GRID_SK;         // 83
    const int rem  = UNITS - base * GRID_SK;  // 4
    int c = blockIdx.x;
    int u   = c * base + (c < rem ? c : rem);
    int end = u + base + (c < rem ? 1 : 0);

    while (u < end) {
        int tile = u >> 7;
        int kc0  = u & (CHT - 1);
        int seg  = CHT - kc0;
        if (seg > end - u) seg = end - u;
        const float* Wt = W + (size_t)tile * 128 * N_NODES;

        float acc[4][4][4];
        #pragma unroll
        for (int i = 0; i < 4; i++)
            #pragma unroll
            for (int j = 0; j < 4; j++)
                #pragma unroll
                for (int q = 0; q < 4; q++) acc[i][j][q] = 0.f;

        int pro = (seg < NST - 1) ? seg : (NST - 1);
        #pragma unroll
        for (int s = 0; s < NST - 1; s++) {
            if (s < pro) {
                fill_stage2(sb, tid, Wt, s, (kc0 + s) * BK2);
                CP_COMMIT();
            }
        }

        int s  = 0;
        int sf = 2;
        for (int kt = 0; kt < seg; kt++) {
            if (kt + 1 < seg) asm volatile("cp.async.wait_group 1;" ::: "memory");
            else              asm volatile("cp.async.wait_group 0;" ::: "memory");
            __syncthreads();

            uint32_t ab = sb + s * STG_BYTES;
            const float* Bst = smB + (size_t)s * (STG_BYTES / 4);

            #pragma unroll
            for (int ksx = 0; ksx < 4; ksx++) {
                uint32_t a[4][4];
                #pragma unroll
                for (int mt = 0; mt < 4; mt++) {
                    uint32_t ad = ab + (uint32_t)(((wm * 64 + mt * 16 + row_sel) * LDS2
                                                   + ksx * 8 + kofs) * 4);
                    ldsm4(a[mt], ad);
                }
                uint32_t bf[4][2];
                #pragma unroll
                for (int nt = 0; nt < 4; nt++) {
                    int rrw = wn * 32 + nt * 8 + (lane >> 2);
                    bf[nt][0] = __float_as_uint(Bst[rrw * LDS2 + ksx * 8 + (lane & 3)]);
                    bf[nt][1] = __float_as_uint(Bst[rrw * LDS2 + ksx * 8 + (lane & 3) + 4]);
                }
                #pragma unroll
                for (int mt = 0; mt < 4; mt++)
                    #pragma unroll
                    for (int nt = 0; nt < 4; nt++)
                        mma_tf32(acc[mt][nt], a[mt], bf[nt]);
            }

            if (kt + 2 < seg) {
                fill_stage2(sb, tid, Wt, sf, (kc0 + kt + 2) * BK2);
                CP_COMMIT();
            }
            s  = (s  == 2) ? 0 : s + 1;
            sf = (sf == 2) ? 0 : sf + 1;
        }

        __syncthreads();

        // epilogue: plain STG to deterministic partial slot
        int slot = (kc0 == 0) ? 0 : (1 + (blockIdx.x & 1));
        float* Pb = g_P3 + (size_t)slot * BATCH * RTOT + (size_t)tile * 128;
        #pragma unroll
        for (int mt = 0; mt < 4; mt++) {
            int m0 = wm * 64 + mt * 16 + (lane >> 2);
            #pragma unroll
            for (int nt = 0; nt < 4; nt++) {
                int n0 = wn * 32 + nt * 8 + ((lane & 3) << 1);
                *(float2*)&Pb[(size_t)m0 * RTOT + n0] =
                    make_float2(acc[mt][nt][0], acc[mt][nt][1]);
                *(float2*)&Pb[(size_t)(m0 + 8) * RTOT + n0] =
                    make_float2(acc[mt][nt][2], acc[mt][nt][3]);
            }
        }
        u += seg;
    }
}

// ---------------- finalize: 3-slot sum, bias-corrected selu*w2, bc + flag ----
#define TF32_RZ_CORR 1.0003522f

__global__ void finalize_kernel(const float* __restrict__ bc,
                                const float* __restrict__ flag,
                                const float* __restrict__ w2,
                                float* __restrict__ out) {
    if (blockIdx.x == 0 && threadIdx.x < 4) g_bars[threadIdx.x] = 0;  // reset for next replay

    int idx = blockIdx.x * blockDim.x + threadIdx.x;   // < 128*4096
    int b = idx >> 12;
    int n = idx & 4095;
    const size_t SL = (size_t)BATCH * RTOT;
    size_t base = (size_t)b * RTOT + n;
    float t0 = (g_P3[base]          + g_P3[SL + base]          + g_P3[2*SL + base])          * TF32_RZ_CORR;
    float t1 = (g_P3[base + 4096]   + g_P3[SL + base + 4096]   + g_P3[2*SL + base + 4096])   * TF32_RZ_CORR;
    float t2 = (g_P3[base + 8192]   + g_P3[SL + base + 8192]   + g_P3[2*SL + base + 8192])   * TF32_RZ_CORR;
    float s = selu_f(t0) * __ldg(&w2[n * 3 + 0])
            + selu_f(t1) * __ldg(&w2[n * 3 + 1])
            + selu_f(t2) * __ldg(&w2[n * 3 + 2]);
    out[idx] = bc[n] + s * flag[n];
}

// ---------------- launch ----------------
extern "C" void kernel_launch(void* const* d_in, const int* in_sizes, int n_in,
                              void* d_out, int out_size) {
    const float* x     = (const float*)d_in[0];
    const float* bc    = (const float*)d_in[1];
    const float* flag  = (const float*)d_in[2];
    const int*   Brows = (const int*)d_in[3];
    const int*   Bcols = (const int*)d_in[4];
    const float* Bvals = (const float*)d_in[5];
    const float* w1    = (const float*)d_in[6];
    const float* w2    = (const float*)d_in[7];
    float* out = (float*)d_out;

    cudaFuncSetAttribute(gemm_sk_kernel,
                         cudaFuncAttributeMaxDynamicSharedMemorySize, GSM_TOTAL);

    prep_kernel<<<NCTA_PREP, 1024>>>(x, bc, flag, Brows, Bcols, Bvals);
    gemm_sk_kernel<<<GRID_SK, 256, GSM_TOTAL>>>(w1);
    finalize_kernel<<<(BATCH * N_NODES) / 256, 256>>>(bc, flag, w2, out);
}

// round 5
// speedup vs baseline: 1.7829x; 1.0548x over previous
#include <cuda_runtime.h>
#include <cuda_fp16.h>
#include <cstdint>

#define N_NODES 4096
#define NNZV    110592
#define BATCH   128
#define RTOT    12288   // 3 * 4096 flattened (k*4096 + n)
#define NCTA_PREP 148

// ---------------- static device scratch ----------------
__device__ int    g_counts[N_NODES];
__device__ int    g_offsets[N_NODES + 1];
__device__ int    g_cursor[N_NODES];
__device__ int    g_ccol[NNZV];
__device__ float  g_cval[NNZV];
__device__ float  g_xT[N_NODES * BATCH];       // xT[m][b]
__device__ __half g_x1h[BATCH * N_NODES];      // x1[b][m]  fp16 (rn)
__device__ float  g_P3[3 * BATCH * RTOT];      // 3 partial slots
__device__ int    g_bars[4];                   // grid barrier counters

// ---------------- helpers ----------------
__device__ __forceinline__ uint32_t smem_u32(const void* p) {
    return (uint32_t)__cvta_generic_to_shared(p);
}

__device__ __forceinline__ void cp16s(uint32_t saddr, const void* g) {
    asm volatile("cp.async.cg.shared.global [%0], [%1], 16;" :: "r"(saddr), "l"(g));
}
#define CP_COMMIT() asm volatile("cp.async.commit_group;" ::: "memory")

__device__ __forceinline__ void ldsm4(uint32_t* r, uint32_t addr) {
    asm volatile("ldmatrix.sync.aligned.m8n8.x4.shared.b16 {%0,%1,%2,%3}, [%4];"
                 : "=r"(r[0]), "=r"(r[1]), "=r"(r[2]), "=r"(r[3]) : "r"(addr));
}

// packs {lo=a, hi=b} as fp16x2
__device__ __forceinline__ uint32_t cvt_f16x2(float a, float b) {
    uint32_t r;
    asm("cvt.rn.f16x2.f32 %0, %2, %1;" : "=r"(r) : "f"(a), "f"(b));
    return r;
}

__device__ __forceinline__ void mma_f16(float* c, const uint32_t* a, const uint32_t* b) {
    asm volatile("mma.sync.aligned.m16n8k16.row.col.f32.f16.f16.f32 "
                 "{%0,%1,%2,%3}, {%4,%5,%6,%7}, {%8,%9}, {%0,%1,%2,%3};"
                 : "+f"(c[0]), "+f"(c[1]), "+f"(c[2]), "+f"(c[3])
                 : "r"(a[0]), "r"(a[1]), "r"(a[2]), "r"(a[3]), "r"(b[0]), "r"(b[1]));
}

__device__ __forceinline__ float selu_f(float v) {
    const float scale = 1.0507009873554805f;
    const float alpha = 1.6732632423543772f;
    return v > 0.f ? scale * v : scale * alpha * expm1f(v);
}

__device__ __forceinline__ void gbar(int k) {
    __syncthreads();
    if (threadIdx.x == 0) {
        __threadfence();
        atomicAdd(&g_bars[k], 1);
        for (;;) {
            int v;
            asm volatile("ld.acquire.gpu.global.s32 %0, [%1];"
                         : "=r"(v) : "l"(&g_bars[k]) : "memory");
            if (v >= NCTA_PREP) break;
            __nanosleep(64);
        }
    }
    __syncthreads();
}

// ---------------- fused preprocessing kernel ----------------
__global__ void __launch_bounds__(1024, 1) prep_kernel(
    const float* __restrict__ x,
    const float* __restrict__ bc,
    const float* __restrict__ flag,
    const int*   __restrict__ rows,
    const int*   __restrict__ cols,
    const float* __restrict__ vals)
{
    __shared__ union {
        float t4[4][32][33];
        int   sc[1024];
        float xr[32][129];
    } sh;

    const int tid = threadIdx.x;
    const int cta = blockIdx.x;
    const int gth = NCTA_PREP * 1024;
    const int gid = cta * 1024 + tid;

    // ---- p0: zero counts + P3 slots 1&2, transpose x -> xT ----
    for (int i = gid; i < N_NODES; i += gth) g_counts[i] = 0;
    {
        float4* p4 = (float4*)(g_P3 + (size_t)BATCH * RTOT);
        const int tot = 2 * BATCH * RTOT / 4;
        for (int i = gid; i < tot; i += gth) p4[i] = make_float4(0.f, 0.f, 0.f, 0.f);
    }
    {
        int sub = tid >> 8;
        int t2  = tid & 255;
        int tx  = t2 & 31;
        int ty  = t2 >> 5;
        int tix = sub * NCTA_PREP + cta;
        bool act = tix < 512;
        int bm = (tix & 127) * 32;
        int bb = (tix >> 7) * 32;
        if (act) {
            #pragma unroll
            for (int i = 0; i < 32; i += 8)
                sh.t4[sub][ty + i][tx] = x[(size_t)(bb + ty + i) * N_NODES + bm + tx];
        }
        __syncthreads();
        if (act) {
            #pragma unroll
            for (int i = 0; i < 32; i += 8)
                g_xT[(size_t)(bm + ty + i) * BATCH + bb + tx] = sh.t4[sub][tx][ty + i];
        }
    }
    gbar(0);

    // ---- p1: count ----
    for (int i = gid; i < NNZV; i += gth) atomicAdd(&g_counts[rows[i]], 1);
    gbar(1);

    // ---- p2: scan (CTA0) ----
    if (cta == 0) {
        int t = tid;
        int c0 = g_counts[4 * t + 0];
        int c1 = g_counts[4 * t + 1];
        int c2 = g_counts[4 * t + 2];
        int c3 = g_counts[4 * t + 3];
        int local = c0 + c1 + c2 + c3;
        sh.sc[t] = local;
        __syncthreads();
        for (int off = 1; off < 1024; off <<= 1) {
            int v = (t >= off) ? sh.sc[t - off] : 0;
            __syncthreads();
            sh.sc[t] += v;
            __syncthreads();
        }
        int excl = sh.sc[t] - local;
        int o0 = excl, o1 = o0 + c0, o2 = o1 + c1, o3 = o2 + c2;
        g_offsets[4 * t + 0] = o0; g_cursor[4 * t + 0] = o0;
        g_offsets[4 * t + 1] = o1; g_cursor[4 * t + 1] = o1;
        g_offsets[4 * t + 2] = o2; g_cursor[4 * t + 2] = o2;
        g_offsets[4 * t + 3] = o3; g_cursor[4 * t + 3] = o3;
        if (t == 1023) g_offsets[N_NODES] = sh.sc[1023];
    }
    gbar(2);

    // ---- p3: scatter ----
    for (int i = gid; i < NNZV; i += gth) {
        int r = rows[i];
        int p = atomicAdd(&g_cursor[r], 1);
        g_ccol[p] = cols[i];
        g_cval[p] = vals[i];
    }
    gbar(3);

    // ---- p4: spmv -> x1 fp16 (smem-transposed coalesced store) ----
    const int w    = tid >> 5;
    const int lane = tid & 31;
    for (int rb = cta; rb < N_NODES / 32; rb += NCTA_PREP) {
        int m = rb * 32 + w;
        int s = g_offsets[m];
        int e = g_offsets[m + 1];
        float a0 = 0.f, a1 = 0.f, a2 = 0.f, a3 = 0.f;
        for (int j = s; j < e; j++) {
            int   c = __ldg(&g_ccol[j]);
            float v = __ldg(&g_cval[j]);
            const float* xr = g_xT + (size_t)c * BATCH;
            a0 += v * xr[lane];
            a1 += v * xr[lane + 32];
            a2 += v * xr[lane + 64];
            a3 += v * xr[lane + 96];
        }
        float f = flag[m], bv = bc[m];
        sh.xr[w][lane]      = bv + a0 * f;
        sh.xr[w][lane + 32] = bv + a1 * f;
        sh.xr[w][lane + 64] = bv + a2 * f;
        sh.xr[w][lane + 96] = bv + a3 * f;
        __syncthreads();
        {   // x1h[b][rb*32+mq .. +4): 4 consecutive m as 2x f16x2
            int b  = tid >> 3;
            int mq = (tid & 7) * 4;
            uint32_t lo = cvt_f16x2(sh.xr[mq + 0][b], sh.xr[mq + 1][b]);
            uint32_t hi = cvt_f16x2(sh.xr[mq + 2][b], sh.xr[mq + 3][b]);
            *(uint2*)&g_x1h[(size_t)b * N_NODES + rb * 32 + mq] = make_uint2(lo, hi);
        }
        __syncthreads();
    }
}

// ---------------- stream-K fp16 mma.sync GEMM ----------------
// D[m=batch][n=W-row] = sum_k x1[m][k] * W[n][k]
#define BK2   32
// A stage: 128 rows x 32 fp16, row stride 80B (64B data + 16B pad)
#define AROWB 80
#define ASTG  (128 * AROWB)           // 10240
// B stage: 128 rows x 36 f32 (32 + 4 pad)
#define LDS2  36
#define BROWB (LDS2 * 4)              // 144
#define BSTG  (128 * BROWB)           // 18432
#define NST   3
#define B_OFF (NST * ASTG)            // 30720
#define GSM_TOTAL (NST * (ASTG + BSTG))   // 86016
#define CHT   (N_NODES / BK2)         // 128
#define NTILE (RTOT / 128)            // 96
#define UNITS (NTILE * CHT)           // 12288
#define GRID_SK 148

__device__ __forceinline__ void fill_stage2(uint32_t sb, int tid,
                                            const float* __restrict__ Wt,
                                            int s, int kk) {
    uint32_t ab = sb + s * ASTG;
    uint32_t bb = sb + B_OFF + s * BSTG;
    // A: 512 x 16B (2/thread), fp16 source
    #pragma unroll
    for (int j = 0; j < 2; j++) {
        int id  = tid + j * 256;
        int row = id >> 2;
        int sg  = id & 3;
        cp16s(ab + (uint32_t)(row * AROWB + sg * 16),
              g_x1h + (size_t)row * N_NODES + kk + sg * 8);
    }
    // B: 1024 x 16B (4/thread), f32 source
    #pragma unroll
    for (int j = 0; j < 4; j++) {
        int id  = tid + j * 256;
        int row = id >> 3;
        int sg  = id & 7;
        cp16s(bb + (uint32_t)(row * BROWB + sg * 16),
              Wt + (size_t)row * N_NODES + kk + sg * 4);
    }
}

__global__ void __launch_bounds__(256) gemm_sk_kernel(const float* __restrict__ W) {
    extern __shared__ char sm2[];
    uint32_t sb = smem_u32(sm2);
    float* smB = (float*)(sm2 + B_OFF);

    int tid  = threadIdx.x;
    int lane = tid & 31;
    int warp = tid >> 5;
    int wm = warp >> 2;                 // 0..1 (64 batch-rows)
    int wn = warp & 3;                  // 0..3 (32 W-rows)

    const int base = UNITS / GRID_SK;         // 83
    const int rem  = UNITS - base * GRID_SK;  // 4
    int c = blockIdx.x;
    int u   = c * base + (c < rem ? c : rem);
    int end = u + base + (c < rem ? 1 : 0);

    while (u < end) {
        int tile = u >> 7;
        int kc0  = u & (CHT - 1);
        int seg  = CHT - kc0;
        if (seg > end - u) seg = end - u;
        const float* Wt = W + (size_t)tile * 128 * N_NODES;

        float acc[4][4][4];
        #pragma unroll
        for (int i = 0; i < 4; i++)
            #pragma unroll
            for (int j = 0; j < 4; j++)
                #pragma unroll
                for (int q = 0; q < 4; q++) acc[i][j][q] = 0.f;

        int pro = (seg < NST - 1) ? seg : (NST - 1);
        #pragma unroll
        for (int s = 0; s < NST - 1; s++) {
            if (s < pro) {
                fill_stage2(sb, tid, Wt, s, (kc0 + s) * BK2);
                CP_COMMIT();
            }
        }

        int s  = 0;
        int sf = 2;
        for (int kt = 0; kt < seg; kt++) {
            if (kt + 1 < seg) asm volatile("cp.async.wait_group 1;" ::: "memory");
            else              asm volatile("cp.async.wait_group 0;" ::: "memory");
            __syncthreads();

            uint32_t ab = sb + s * ASTG;
            const float* Bst = smB + (size_t)s * (BSTG / 4);

            #pragma unroll
            for (int ksx = 0; ksx < 2; ksx++) {      // two K=16 steps
                // A frags via ldsm.x4 on fp16 smem
                uint32_t a[4][4];
                #pragma unroll
                for (int mt = 0; mt < 4; mt++) {
                    uint32_t ad = ab + (uint32_t)((wm * 64 + mt * 16 + (lane & 15)) * AROWB
                                                  + ksx * 32 + (lane >> 4) * 16);
                    ldsm4(a[mt], ad);
                }
                // B frags: LDS.64 f32 pairs + cvt
                uint32_t bf[4][2];
                #pragma unroll
                for (int nt = 0; nt < 4; nt++) {
                    int n = wn * 32 + nt * 8 + (lane >> 2);
                    int kb = ksx * 16 + (lane & 3) * 2;
                    const float* bp = Bst + n * LDS2 + kb;
                    float2 lo = *(const float2*)bp;
                    float2 hi = *(const float2*)(bp + 8);
                    bf[nt][0] = cvt_f16x2(lo.x, lo.y);
                    bf[nt][1] = cvt_f16x2(hi.x, hi.y);
                }
                #pragma unroll
                for (int mt = 0; mt < 4; mt++)
                    #pragma unroll
                    for (int nt = 0; nt < 4; nt++)
                        mma_f16(acc[mt][nt], a[mt], bf[nt]);
            }

            if (kt + 2 < seg) {
                fill_stage2(sb, tid, Wt, sf, (kc0 + kt + 2) * BK2);
                CP_COMMIT();
            }
            s  = (s  == 2) ? 0 : s + 1;
            sf = (sf == 2) ? 0 : sf + 1;
        }

        __syncthreads();

        // epilogue: STG to deterministic partial slot
        int slot = (kc0 == 0) ? 0 : (1 + (blockIdx.x & 1));
        float* Pb = g_P3 + (size_t)slot * BATCH * RTOT + (size_t)tile * 128;
        #pragma unroll
        for (int mt = 0; mt < 4; mt++) {
            int m0 = wm * 64 + mt * 16 + (lane >> 2);
            #pragma unroll
            for (int nt = 0; nt < 4; nt++) {
                int n0 = wn * 32 + nt * 8 + ((lane & 3) << 1);
                *(float2*)&Pb[(size_t)m0 * RTOT + n0] =
                    make_float2(acc[mt][nt][0], acc[mt][nt][1]);
                *(float2*)&Pb[(size_t)(m0 + 8) * RTOT + n0] =
                    make_float2(acc[mt][nt][2], acc[mt][nt][3]);
            }
        }
        u += seg;
    }
}

// ---------------- finalize ----------------
__global__ void finalize_kernel(const float* __restrict__ bc,
                                const float* __restrict__ flag,
                                const float* __restrict__ w2,
                                float* __restrict__ out) {
    if (blockIdx.x == 0 && threadIdx.x < 4) g_bars[threadIdx.x] = 0;

    int idx = blockIdx.x * blockDim.x + threadIdx.x;
    int b = idx >> 12;
    int n = idx & 4095;
    const size_t SL = (size_t)BATCH * RTOT;
    size_t base = (size_t)b * RTOT + n;
    float t0 = g_P3[base]        + g_P3[SL + base]        + g_P3[2*SL + base];
    float t1 = g_P3[base + 4096] + g_P3[SL + base + 4096] + g_P3[2*SL + base + 4096];
    float t2 = g_P3[base + 8192] + g_P3[SL + base + 8192] + g_P3[2*SL + base + 8192];
    float s = selu_f(t0) * __ldg(&w2[n * 3 + 0])
            + selu_f(t1) * __ldg(&w2[n * 3 + 1])
            + selu_f(t2) * __ldg(&w2[n * 3 + 2]);
    out[idx] = bc[n] + s * flag[n];
}

// ---------------- launch ----------------
extern "C" void kernel_launch(void* const* d_in, const int* in_sizes, int n_in,
                              void* d_out, int out_size) {
    const float* x     = (const float*)d_in[0];
    const float* bc    = (const float*)d_in[1];
    const float* flag  = (const float*)d_in[2];
    const int*   Brows = (const int*)d_in[3];
    const int*   Bcols = (const int*)d_in[4];
    const float* Bvals = (const float*)d_in[5];
    const float* w1    = (const float*)d_in[6];
    const float* w2    = (const float*)d_in[7];
    float* out = (float*)d_out;

    cudaFuncSetAttribute(gemm_sk_kernel,
                         cudaFuncAttributeMaxDynamicSharedMemorySize, GSM_TOTAL);

    prep_kernel<<<NCTA_PREP, 1024>>>(x, bc, flag, Brows, Bcols, Bvals);
    gemm_sk_kernel<<<GRID_SK, 256, GSM_TOTAL>>>(w1);
    finalize_kernel<<<(BATCH * N_NODES) / 256, 256>>>(bc, flag, w2, out);
}